// round 3
// baseline (speedup 1.0000x reference)
#include <cuda_runtime.h>

// B3-spline UWT (a trous), J=3. x:(16,1024,1024)f32 -> (16,4,1024,1024)f32.
// Per-level fused separable conv; vertical pass in registers (direct gmem
// column windows), only the mid buffer lives in smem.

#define HH 1024
#define WW 1024
#define BB 16
#define HW (HH * WW)

__device__ float g_buf0[BB * HW];
__device__ float g_buf1[BB * HW];

__device__ __forceinline__ int refl(int i, int L) {
    if (i < 0) i = -i;
    if (i >= L) i = 2 * L - 2 - i;
    return i;
}

__device__ __forceinline__ float4 f4fma(float4 a, float w, float4 v) {
    a.x += w * v.x; a.y += w * v.y; a.z += w * v.z; a.w += w * v.w;
    return a;
}

template <int DIL>
__global__ __launch_bounds__(256) void uwt_level(
    const float* __restrict__ in,     // (B,H,W) bstride HW
    float* __restrict__ detail,       // plane base, bstride 4*HW
    float* __restrict__ smooth,       // scratch (bstride HW) or c_J (4*HW)
    int sm_bs)
{
    constexpr int TX = 128, TY = 32, R = 8;
    constexpr int HXv  = (DIL == 4) ? 8 : 4;   // x halo (4-aligned, >= 2*DIL)
    constexpr int MIDC = TX + 2 * HXv;          // mid columns (136 / 144)
    constexpr int MIDV = MIDC / 4;              // vec4 columns (34 / 36)
    constexpr int NW   = R + 4 * DIL;           // vertical window rows
    constexpr int SMP  = MIDC + 4;              // padded smem row stride
    constexpr int NT   = MIDV * (TY / R);       // vertical tasks (136 / 144)
    constexpr int NV2  = (DIL == 4) ? 6 : 4;    // horiz window vec4 loads

    __shared__ float s_mid[TY][SMP];

    const int b   = blockIdx.z;
    const int ty0 = blockIdx.y * TY;
    const int tx0 = blockIdx.x * TX;
    const int tid = threadIdx.x;

    const float* base = in + b * HW;
    const bool intX = (tx0 >= HXv) && (tx0 + TX + HXv <= WW);

    const float w0 = 0.0625f, w1 = 0.25f, w2 = 0.375f;
    const float W5[5] = { w0, w1, w2, w1, w0 };

    // ---- Phase 1: vertical 5-tap conv, gmem -> registers -> s_mid ----
    if (tid < NT) {
        const int vc    = tid % MIDV;
        const int rg    = tid / MIDV;
        const int gx0   = tx0 - HXv + vc * 4;
        const int ybase = ty0 + rg * R - 2 * DIL;

        float4 acc[R];
        #pragma unroll
        for (int r = 0; r < R; r++) acc[r] = make_float4(0.f, 0.f, 0.f, 0.f);

        #pragma unroll
        for (int l = 0; l < NW; l++) {
            const int gy = refl(ybase + l, HH);
            const float* row = base + gy * WW;
            float4 v;
            if (intX) {
                v = *(const float4*)(row + gx0);
            } else {
                v.x = row[refl(gx0 + 0, WW)];
                v.y = row[refl(gx0 + 1, WW)];
                v.z = row[refl(gx0 + 2, WW)];
                v.w = row[refl(gx0 + 3, WW)];
            }
            #pragma unroll
            for (int k = 0; k < 5; k++) {
                const int r = l - k * DIL;
                if (r >= 0 && r < R) acc[r] = f4fma(acc[r], W5[k], v);
            }
        }
        #pragma unroll
        for (int r = 0; r < R; r++)
            *(float4*)&s_mid[rg * R + r][vc * 4] = acc[r];
    }
    __syncthreads();

    // ---- Phase 2: horizontal 5-tap conv + detail, 8 outputs/thread/row ----
    const int p  = tid & 15;       // pair of vec4 output cols: floats [8p, 8p+8)
    const int r0 = tid >> 4;       // rows r0, r0+16
    const int c0 = 8 * p;

    #pragma unroll
    for (int rr = r0; rr < TY; rr += 16) {
        float t[4 * NV2];
        #pragma unroll
        for (int v = 0; v < NV2; v++)
            *(float4*)&t[4 * v] = *(const float4*)&s_mid[rr][c0 + 4 * v];

        const int off = (ty0 + rr) * WW + (tx0 + c0);
        float4 prev0 = *(const float4*)(base + off);
        float4 prev1 = *(const float4*)(base + off + 4);

        float o[8];
        #pragma unroll
        for (int j = 0; j < 8; j++) {
            const int ci = HXv + j;   // center index within window t[]
            o[j] = w0 * (t[ci - 2 * DIL] + t[ci + 2 * DIL])
                 + w1 * (t[ci -     DIL] + t[ci +     DIL])
                 + w2 *  t[ci];
        }

        float4 sm0 = make_float4(o[0], o[1], o[2], o[3]);
        float4 sm1 = make_float4(o[4], o[5], o[6], o[7]);
        float4 d0  = make_float4(prev0.x - o[0], prev0.y - o[1],
                                 prev0.z - o[2], prev0.w - o[3]);
        float4 d1  = make_float4(prev1.x - o[4], prev1.y - o[5],
                                 prev1.z - o[6], prev1.w - o[7]);

        float* dp = detail + b * 4 * HW + off;
        float* sp = smooth + b * sm_bs  + off;
        *(float4*)(dp)     = d0;
        *(float4*)(dp + 4) = d1;
        *(float4*)(sp)     = sm0;
        *(float4*)(sp + 4) = sm1;
    }
}

extern "C" void kernel_launch(void* const* d_in, const int* in_sizes, int n_in,
                              void* d_out, int out_size)
{
    (void)in_sizes; (void)n_in; (void)out_size;
    const float* x = (const float*)d_in[0];
    float* out = (float*)d_out;

    float *b0, *b1;
    cudaGetSymbolAddress((void**)&b0, g_buf0);
    cudaGetSymbolAddress((void**)&b1, g_buf1);

    dim3 grid(WW / 128, HH / 32, BB);
    dim3 block(256);

    uwt_level<1><<<grid, block>>>(x,  out + 0 * HW, b0, HW);
    uwt_level<2><<<grid, block>>>(b0, out + 1 * HW, b1, HW);
    uwt_level<4><<<grid, block>>>(b1, out + 2 * HW, out + 3 * HW, 4 * HW);
}

// round 4
// speedup vs baseline: 1.0043x; 1.0043x over previous
#include <cuda_runtime.h>

// B3-spline UWT (a trous), J=3. x:(16,1024,1024)f32 -> (16,4,1024,1024)f32.
// Per-level fused separable conv; vertical pass in registers (direct gmem
// column windows, R=4 rows/task, full-block task loop); only mid buf in smem.

#define HH 1024
#define WW 1024
#define BB 16
#define HW (HH * WW)

__device__ float g_buf0[BB * HW];
__device__ float g_buf1[BB * HW];

__device__ __forceinline__ int refl(int i, int L) {
    if (i < 0) i = -i;
    if (i >= L) i = 2 * L - 2 - i;
    return i;
}

__device__ __forceinline__ float4 f4fma(float4 a, float w, float4 v) {
    a.x += w * v.x; a.y += w * v.y; a.z += w * v.z; a.w += w * v.w;
    return a;
}

template <int DIL>
__global__ __launch_bounds__(256) void uwt_level(
    const float* __restrict__ in,     // (B,H,W) bstride HW
    float* __restrict__ detail,       // plane base, bstride 4*HW
    float* __restrict__ smooth,       // scratch (bstride HW) or c_J (4*HW)
    int sm_bs)
{
    constexpr int TX = 128, TY = 32, R = 4;
    constexpr int HXv  = (DIL == 4) ? 8 : 4;    // x halo (4-aligned, >= 2*DIL)
    constexpr int MIDC = TX + 2 * HXv;          // 136 / 144
    constexpr int MIDV = MIDC / 4;              // 34 / 36
    constexpr int NW   = R + 4 * DIL;           // 8 / 12 / 20
    constexpr int SMP  = MIDC + 4;
    constexpr int NT   = MIDV * (TY / R);       // 272 / 288
    constexpr int NV2  = (DIL == 4) ? 6 : 4;    // horiz window vec4 loads

    __shared__ float s_mid[TY][SMP];

    const int b   = blockIdx.z;
    const int ty0 = blockIdx.y * TY;
    const int tx0 = blockIdx.x * TX;
    const int tid = threadIdx.x;

    const float* base = in + b * HW;
    const bool intX = (tx0 >= HXv) && (tx0 + TX + HXv <= WW);

    const float w0 = 0.0625f, w1 = 0.25f, w2 = 0.375f;
    const float W5[5] = { w0, w1, w2, w1, w0 };

    // ---- Phase 1: vertical 5-tap conv, gmem -> regs -> s_mid (all threads) ----
    for (int i = tid; i < NT; i += 256) {
        const int vc    = i % MIDV;
        const int rg    = i / MIDV;
        const int gx0   = tx0 - HXv + vc * 4;
        const int ybase = ty0 + rg * R - 2 * DIL;

        float4 acc[R];
        #pragma unroll
        for (int r = 0; r < R; r++) acc[r] = make_float4(0.f, 0.f, 0.f, 0.f);

        #pragma unroll
        for (int l = 0; l < NW; l++) {
            const int gy = refl(ybase + l, HH);
            const float* row = base + gy * WW;
            float4 v;
            if (intX) {
                v = *(const float4*)(row + gx0);
            } else {
                v.x = row[refl(gx0 + 0, WW)];
                v.y = row[refl(gx0 + 1, WW)];
                v.z = row[refl(gx0 + 2, WW)];
                v.w = row[refl(gx0 + 3, WW)];
            }
            #pragma unroll
            for (int k = 0; k < 5; k++) {
                const int r = l - k * DIL;
                if (r >= 0 && r < R) acc[r] = f4fma(acc[r], W5[k], v);
            }
        }
        #pragma unroll
        for (int r = 0; r < R; r++)
            *(float4*)&s_mid[rg * R + r][vc * 4] = acc[r];
    }
    __syncthreads();

    // ---- Phase 2: horizontal 5-tap conv + detail, 8 outputs/thread/row ----
    const int p  = tid & 15;       // output float cols [8p, 8p+8)
    const int r0 = tid >> 4;       // rows r0, r0+16
    const int c0 = 8 * p;

    #pragma unroll
    for (int rr = r0; rr < TY; rr += 16) {
        float t[4 * NV2];
        #pragma unroll
        for (int v = 0; v < NV2; v++)
            *(float4*)&t[4 * v] = *(const float4*)&s_mid[rr][c0 + 4 * v];

        const int off = (ty0 + rr) * WW + (tx0 + c0);
        float4 prev0 = *(const float4*)(base + off);
        float4 prev1 = *(const float4*)(base + off + 4);

        float o[8];
        #pragma unroll
        for (int j = 0; j < 8; j++) {
            const int ci = HXv + j;
            o[j] = w0 * (t[ci - 2 * DIL] + t[ci + 2 * DIL])
                 + w1 * (t[ci -     DIL] + t[ci +     DIL])
                 + w2 *  t[ci];
        }

        float4 sm0 = make_float4(o[0], o[1], o[2], o[3]);
        float4 sm1 = make_float4(o[4], o[5], o[6], o[7]);
        float4 d0  = make_float4(prev0.x - o[0], prev0.y - o[1],
                                 prev0.z - o[2], prev0.w - o[3]);
        float4 d1  = make_float4(prev1.x - o[4], prev1.y - o[5],
                                 prev1.z - o[6], prev1.w - o[7]);

        float* dp = detail + b * 4 * HW + off;
        float* sp = smooth + b * sm_bs  + off;
        *(float4*)(dp)     = d0;
        *(float4*)(dp + 4) = d1;
        *(float4*)(sp)     = sm0;
        *(float4*)(sp + 4) = sm1;
    }
}

extern "C" void kernel_launch(void* const* d_in, const int* in_sizes, int n_in,
                              void* d_out, int out_size)
{
    (void)in_sizes; (void)n_in; (void)out_size;
    const float* x = (const float*)d_in[0];
    float* out = (float*)d_out;

    float *b0, *b1;
    cudaGetSymbolAddress((void**)&b0, g_buf0);
    cudaGetSymbolAddress((void**)&b1, g_buf1);

    dim3 grid(WW / 128, HH / 32, BB);
    dim3 block(256);

    uwt_level<1><<<grid, block>>>(x,  out + 0 * HW, b0, HW);
    uwt_level<2><<<grid, block>>>(b0, out + 1 * HW, b1, HW);
    uwt_level<4><<<grid, block>>>(b1, out + 2 * HW, out + 3 * HW, 4 * HW);
}

// round 5
// speedup vs baseline: 1.3403x; 1.3346x over previous
#include <cuda_runtime.h>

// B3-spline UWT (a trous), J=3. x:(16,1024,1024)f32 -> (16,4,1024,1024)f32.
// Per level: horizontal 5-tap conv from gmem (register windows) -> smem rows
// (incl. y-halo), then vertical 5-tap from smem; detail = prev - smooth.

#define HH 1024
#define WW 1024
#define BB 16
#define HW (HH * WW)

__device__ float g_buf0[BB * HW];
__device__ float g_buf1[BB * HW];

__device__ __forceinline__ int refl(int i, int L) {
    if (i < 0) i = -i;
    if (i >= L) i = 2 * L - 2 - i;
    return i;
}

template <int DIL>
__global__ __launch_bounds__(256) void uwt_level(
    const float* __restrict__ in,     // (B,H,W) bstride HW
    float* __restrict__ detail,       // plane base, bstride 4*HW
    float* __restrict__ smooth,       // scratch (bstride HW) or c_J (4*HW)
    int sm_bs)
{
    constexpr int TX = 128, TY = 32;
    constexpr int HY   = 2 * DIL;
    constexpr int SY   = TY + 2 * HY;            // 36 / 40 / 48
    constexpr int AOFF = (DIL == 4) ? 8 : 4;     // aligned window back-offset
    constexpr int NVA  = (DIL == 4) ? 5 : 3;     // float4 loads per window
    constexpr int SMP  = TX + 4;                 // smem row stride (floats)

    __shared__ float s_h[SY][SMP];

    const int b   = blockIdx.z;
    const int ty0 = blockIdx.y * TY;
    const int tx0 = blockIdx.x * TX;
    const int tid = threadIdx.x;

    const float* base = in + b * HW;
    const int c0  = 4 * (tid & 31);              // warp spans full 128-col row
    const int gx0 = tx0 + c0;
    const bool intX = (tx0 >= AOFF) && (tx0 + TX + AOFF <= WW);

    const float w0 = 0.0625f, w1 = 0.25f, w2 = 0.375f;

    // ---- Phase A: horizontal conv, gmem -> regs -> s_h (SY rows incl. halo)
    for (int r = (tid >> 5); r < SY; r += 8) {
        const int gy = refl(ty0 - HY + r, HH);
        const float* row = base + gy * WW;

        float t[4 * NVA];
        if (intX) {
            #pragma unroll
            for (int v = 0; v < NVA; v++)
                *(float4*)&t[4 * v] = *(const float4*)(row + gx0 - AOFF + 4 * v);
        } else {
            #pragma unroll
            for (int j = 0; j < 4 * NVA; j++)
                t[j] = row[refl(gx0 - AOFF + j, WW)];
        }

        float4 h;
        {
            const int ci = AOFF;
            h.x = w0 * (t[ci + 0 - 2*DIL] + t[ci + 0 + 2*DIL])
                + w1 * (t[ci + 0 -   DIL] + t[ci + 0 +   DIL])
                + w2 *  t[ci + 0];
            h.y = w0 * (t[ci + 1 - 2*DIL] + t[ci + 1 + 2*DIL])
                + w1 * (t[ci + 1 -   DIL] + t[ci + 1 +   DIL])
                + w2 *  t[ci + 1];
            h.z = w0 * (t[ci + 2 - 2*DIL] + t[ci + 2 + 2*DIL])
                + w1 * (t[ci + 2 -   DIL] + t[ci + 2 +   DIL])
                + w2 *  t[ci + 2];
            h.w = w0 * (t[ci + 3 - 2*DIL] + t[ci + 3 + 2*DIL])
                + w1 * (t[ci + 3 -   DIL] + t[ci + 3 +   DIL])
                + w2 *  t[ci + 3];
        }
        *(float4*)&s_h[r][c0] = h;
    }
    __syncthreads();

    // ---- Phase B: vertical conv from smem + detail; bank-perfect LDS.128
    #pragma unroll
    for (int rr = (tid >> 5); rr < TY; rr += 8) {
        float4 a0 = *(const float4*)&s_h[rr           ][c0];
        float4 a1 = *(const float4*)&s_h[rr +     DIL ][c0];
        float4 a2 = *(const float4*)&s_h[rr + 2 * DIL ][c0];
        float4 a3 = *(const float4*)&s_h[rr + 3 * DIL ][c0];
        float4 a4 = *(const float4*)&s_h[rr + 4 * DIL ][c0];

        float4 sm;
        sm.x = w0 * (a0.x + a4.x) + w1 * (a1.x + a3.x) + w2 * a2.x;
        sm.y = w0 * (a0.y + a4.y) + w1 * (a1.y + a3.y) + w2 * a2.y;
        sm.z = w0 * (a0.z + a4.z) + w1 * (a1.z + a3.z) + w2 * a2.z;
        sm.w = w0 * (a0.w + a4.w) + w1 * (a1.w + a3.w) + w2 * a2.w;

        const int off = (ty0 + rr) * WW + gx0;
        float4 prev = *(const float4*)(base + off);
        float4 dt = make_float4(prev.x - sm.x, prev.y - sm.y,
                                prev.z - sm.z, prev.w - sm.w);

        *(float4*)(detail + b * 4 * HW + off) = dt;
        *(float4*)(smooth + b * sm_bs  + off) = sm;
    }
}

extern "C" void kernel_launch(void* const* d_in, const int* in_sizes, int n_in,
                              void* d_out, int out_size)
{
    (void)in_sizes; (void)n_in; (void)out_size;
    const float* x = (const float*)d_in[0];
    float* out = (float*)d_out;

    float *b0, *b1;
    cudaGetSymbolAddress((void**)&b0, g_buf0);
    cudaGetSymbolAddress((void**)&b1, g_buf1);

    dim3 grid(WW / 128, HH / 32, BB);
    dim3 block(256);

    uwt_level<1><<<grid, block>>>(x,  out + 0 * HW, b0, HW);
    uwt_level<2><<<grid, block>>>(b0, out + 1 * HW, b1, HW);
    uwt_level<4><<<grid, block>>>(b1, out + 2 * HW, out + 3 * HW, 4 * HW);
}